// round 16
// baseline (speedup 1.0000x reference)
#include <cuda_runtime.h>
#include <cuda_bf16.h>
#include <cstdint>

// Problem constants
#define B_ 16
#define T_ 16384
#define D_ 256
#define S_ 4
#define TILE 128
#define KT 64
#define KSPLIT 6               // 48*6 = 288 gram CTAs
#define PITCH 136              // 128 + 8 pad -> conflict-free ldmatrix.trans
#define MS (KT * PITCH)        // elements per smem matrix stage
#define NSTAGE 2
#define NRED 784               // 768 Gvv blocks + 16 Gvy/count blocks

// Scratch (device globals; zero-initialized at load)
__device__ __nv_bfloat16 g_V[(size_t)B_ * T_ * D_];         // normalized V, bf16
__device__ unsigned char g_cls[B_ * T_];                     // speaker class per row
__device__ float g_GvvP[(size_t)48 * KSPLIT * TILE * TILE];  // K-split partials (18.9MB)
__device__ float g_GvyP[512 * 1024];                         // per-block Gvy partials (2MB)
__device__ float g_acc[1];
__device__ unsigned int g_done;
__device__ unsigned int g_rdy[512];   // per-(batch,chunk) readiness flags

// ---------------------------------------------------------------------------
// PTX helpers
// ---------------------------------------------------------------------------
__device__ __forceinline__ void cp16(__nv_bfloat16* dst, const __nv_bfloat16* src) {
    unsigned d = (unsigned)__cvta_generic_to_shared(dst);
    asm volatile("cp.async.cg.shared.global [%0], [%1], 16;\n" :: "r"(d), "l"(src));
}
__device__ __forceinline__ void cp_commit() { asm volatile("cp.async.commit_group;\n"); }
template <int N> __device__ __forceinline__ void cp_wait() {
    asm volatile("cp.async.wait_group %0;\n" :: "n"(N));
}
__device__ __forceinline__ void ldsm4t(uint32_t* r, const __nv_bfloat16* p) {
    unsigned a = (unsigned)__cvta_generic_to_shared(p);
    asm volatile("ldmatrix.sync.aligned.m8n8.x4.trans.shared.b16 {%0,%1,%2,%3}, [%4];\n"
                 : "=r"(r[0]), "=r"(r[1]), "=r"(r[2]), "=r"(r[3]) : "r"(a));
}
__device__ __forceinline__ void mma_bf16(float* c, const uint32_t* a, const uint32_t* b) {
    asm volatile("mma.sync.aligned.m16n8k16.row.col.f32.bf16.bf16.f32 "
                 "{%0,%1,%2,%3},{%4,%5,%6,%7},{%8,%9},{%0,%1,%2,%3};\n"
                 : "+f"(c[0]), "+f"(c[1]), "+f"(c[2]), "+f"(c[3])
                 : "r"(a[0]), "r"(a[1]), "r"(a[2]), "r"(a[3]), "r"(b[0]), "r"(b[1]));
}

// ---------------------------------------------------------------------------
// K1 FUSED: bids 0-511 = norm (R9 body + release flag), bids 512-799 = gram
// (R9 body + acquire poll per 64-row stage). Norm is HBM-bound, gram is
// tensor-bound -> co-residency overlaps the two resource streams.
// Deadlock-free: 296 resident slots > 288 gram CTAs, norm never waits.
// ---------------------------------------------------------------------------
__global__ __launch_bounds__(256, 2) void k_fused(const float* __restrict__ emb,
                                                  const float* __restrict__ lab) {
    extern __shared__ char smraw[];
    int tid = threadIdx.x;
    int wid = tid >> 5, lane = tid & 31;

    if (blockIdx.x < 512) {
        // ================= NORM path =================
        float* sred = reinterpret_cast<float*>(smraw);
        int bid  = blockIdx.x;
        int b    = bid >> 5;
        int ch   = bid & 31;
        int row0 = b * T_ + ch * 512 + wid * 64;

        int s_lo, s_hi;
        {
            float4 lb = reinterpret_cast<const float4*>(lab)[row0 + lane];
            s_lo = lb.y > 0.5f ? 1 : (lb.z > 0.5f ? 2 : (lb.w > 0.5f ? 3 : 0));
            g_cls[row0 + lane] = (unsigned char)s_lo;
            float4 lb2 = reinterpret_cast<const float4*>(lab)[row0 + 32 + lane];
            s_hi = lb2.y > 0.5f ? 1 : (lb2.z > 0.5f ? 2 : (lb2.w > 0.5f ? 3 : 0));
            g_cls[row0 + 32 + lane] = (unsigned char)s_hi;
        }

        float acc[4][8];
        #pragma unroll
        for (int c = 0; c < 4; c++)
            #pragma unroll
            for (int i = 0; i < 8; i++) acc[c][i] = 0.0f;

        #pragma unroll 1
        for (int rb = 0; rb < 64; rb += 4) {
            float4 va[4][2];
            #pragma unroll
            for (int u = 0; u < 4; u++) {
                const float4* src = reinterpret_cast<const float4*>(emb)
                                  + (size_t)(row0 + rb + u) * (D_ / 4) + lane * 2;
                va[u][0] = src[0];
                va[u][1] = src[1];
            }
            float ss[4];
            #pragma unroll
            for (int u = 0; u < 4; u++) {
                float4 v0 = va[u][0], v1 = va[u][1];
                ss[u] = v0.x*v0.x + v0.y*v0.y + v0.z*v0.z + v0.w*v0.w
                      + v1.x*v1.x + v1.y*v1.y + v1.z*v1.z + v1.w*v1.w;
            }
            #pragma unroll
            for (int o = 16; o; o >>= 1) {
                #pragma unroll
                for (int u = 0; u < 4; u++)
                    ss[u] += __shfl_xor_sync(0xffffffffu, ss[u], o);
            }
            #pragma unroll
            for (int u = 0; u < 4; u++) {
                int r = rb + u;
                float sc = 1.0f / fmaxf(sqrtf(ss[u]), 1e-12f);
                float4 v0 = va[u][0], v1 = va[u][1];
                float n0 = v0.x * sc, n1 = v0.y * sc, n2 = v0.z * sc, n3 = v0.w * sc;
                float n4 = v1.x * sc, n5 = v1.y * sc, n6 = v1.z * sc, n7 = v1.w * sc;

                __nv_bfloat162 p0 = __floats2bfloat162_rn(n0, n1);
                __nv_bfloat162 p1 = __floats2bfloat162_rn(n2, n3);
                __nv_bfloat162 p2 = __floats2bfloat162_rn(n4, n5);
                __nv_bfloat162 p3 = __floats2bfloat162_rn(n6, n7);
                uint4 pk;
                pk.x = *reinterpret_cast<uint32_t*>(&p0);
                pk.y = *reinterpret_cast<uint32_t*>(&p1);
                pk.z = *reinterpret_cast<uint32_t*>(&p2);
                pk.w = *reinterpret_cast<uint32_t*>(&p3);
                reinterpret_cast<uint4*>(g_V)[(size_t)(row0 + r) * (D_ / 8) + lane] = pk;

                int s = __shfl_sync(0xffffffffu, r < 32 ? s_lo : s_hi, r & 31);
                #define ACCUM(C) { acc[C][0]+=n0; acc[C][1]+=n1; acc[C][2]+=n2; acc[C][3]+=n3; \
                                   acc[C][4]+=n4; acc[C][5]+=n5; acc[C][6]+=n6; acc[C][7]+=n7; }
                if      (s == 0) ACCUM(0)
                else if (s == 1) ACCUM(1)
                else if (s == 2) ACCUM(2)
                else             ACCUM(3)
                #undef ACCUM
            }
        }

        // release: make g_V stores visible, then publish readiness
        #pragma unroll
        for (int c = 0; c < 4; c++)
            #pragma unroll
            for (int i = 0; i < 8; i++)
                sred[wid * 1024 + (c * 8 + i) * 32 + lane] = acc[c][i];
        __threadfence();
        __syncthreads();
        if (tid == 0) atomicExch(&g_rdy[bid], 1u);

        float* gp = g_GvyP + (size_t)bid * 1024;
        #pragma unroll
        for (int j = 0; j < 4; j++) {
            int o = tid + 256 * j;
            float sum = 0.0f;
            #pragma unroll
            for (int w = 0; w < 8; w++) sum += sred[w * 1024 + o];
            gp[o] = sum;
        }
    } else {
        // ================= GRAM path =================
        __nv_bfloat16* sm = reinterpret_cast<__nv_bfloat16*>(smraw);
        int gbid = blockIdx.x - 512;
        int bt   = gbid / KSPLIT;
        int kc   = gbid % KSPLIT;
        int b    = bt / 3, tile = bt % 3;
        int ti   = (tile == 0) ? 0 : 1;
        int tj   = (tile == 2) ? 1 : 0;
        bool diag = (ti == tj);
        int it0  = (kc < 4) ? 43 * kc : 172 + 42 * (kc - 4);
        int NIT  = (kc < 4) ? 43 : 42;
        const __nv_bfloat16* gv = g_V + (size_t)b * T_ * D_;

        int wm = (wid & 3) * 32;
        int wn = (wid >> 2) * 64;
        int q = lane >> 3, rr = lane & 7;

        float acc[2][8][4];
        #pragma unroll
        for (int mi = 0; mi < 2; mi++)
            #pragma unroll
            for (int ni = 0; ni < 8; ni++)
                #pragma unroll
                for (int x = 0; x < 4; x++) acc[mi][ni][x] = 0.0f;

        auto load_stage = [&](int st, int iter) {
            // acquire: wait until the 512-row chunk holding this stage is ready
            unsigned fidx = (unsigned)(b * 32 + ((it0 + iter) >> 3));
            if (lane == 0) {
                while (((volatile unsigned*)g_rdy)[fidx] == 0u) __nanosleep(64);
            }
            __syncwarp();

            size_t kofs = (size_t)(it0 + iter) * KT;
            const __nv_bfloat16* ga = gv + kofs * D_ + ti * TILE;
            __nv_bfloat16* sa = sm + st * MS;
            #pragma unroll
            for (int i = 0; i < 4; i++) {
                int c = tid + i * 256;
                int r = c >> 4, cc = c & 15;
                cp16(sa + r * PITCH + cc * 8, ga + r * D_ + cc * 8);
            }
            if (!diag) {
                const __nv_bfloat16* gb = gv + kofs * D_ + tj * TILE;
                __nv_bfloat16* sb = sm + (NSTAGE + st) * MS;
                #pragma unroll
                for (int i = 0; i < 4; i++) {
                    int c = tid + i * 256;
                    int r = c >> 4, cc = c & 15;
                    cp16(sb + r * PITCH + cc * 8, gb + r * D_ + cc * 8);
                }
            }
            cp_commit();
        };

        load_stage(0, 0);

        for (int it = 0; it < NIT; ++it) {
            cp_wait<0>();
            __syncthreads();
            if (it + 1 < NIT) load_stage((it + 1) & 1, it + 1);

            int st = it & 1;
            const __nv_bfloat16* As = sm + st * MS;
            const __nv_bfloat16* Bs = diag ? As : sm + (NSTAGE + st) * MS;
            #pragma unroll
            for (int ks = 0; ks < KT / 16; ++ks) {
                uint32_t af[2][4];
                #pragma unroll
                for (int mi = 0; mi < 2; mi++) {
                    int dm   = wm + mi * 16;
                    int krow = ks * 16 + ((q & 2) ? 8 : 0) + rr;
                    int col  = dm + ((q & 1) ? 8 : 0);
                    ldsm4t(af[mi], As + krow * PITCH + col);
                }
                uint32_t bfr[8][2];
                #pragma unroll
                for (int j = 0; j < 4; j++) {
                    int n0   = wn + j * 16;
                    int krow = ks * 16 + ((q & 1) ? 8 : 0) + rr;
                    int col  = n0 + ((q & 2) ? 8 : 0);
                    uint32_t t4[4];
                    ldsm4t(t4, Bs + krow * PITCH + col);
                    bfr[2 * j][0]     = t4[0]; bfr[2 * j][1]     = t4[1];
                    bfr[2 * j + 1][0] = t4[2]; bfr[2 * j + 1][1] = t4[3];
                }
                #pragma unroll
                for (int mi = 0; mi < 2; mi++)
                    #pragma unroll
                    for (int ni = 0; ni < 8; ni++)
                        mma_bf16(acc[mi][ni], af[mi], bfr[ni]);
            }
        }

        // Epilogue: plain stores of this K-split's partial tile
        int gid = lane >> 2, tig = lane & 3;
        float* gdst = g_GvvP + ((size_t)bt * KSPLIT + kc) * TILE * TILE;
        #pragma unroll
        for (int mi = 0; mi < 2; mi++) {
            #pragma unroll
            for (int ni = 0; ni < 8; ni++) {
                int m = wm + mi * 16 + gid;
                int n = wn + ni * 8 + tig * 2;
                float* p = gdst + m * TILE + n;
                p[0] = acc[mi][ni][0];
                p[1] = acc[mi][ni][1];
                p[8 * TILE + 0] = acc[mi][ni][2];
                p[8 * TILE + 1] = acc[mi][ni][3];
            }
        }
    }
}

// ---------------------------------------------------------------------------
// K3: parallel reduction + final output. 784 blocks. Gvy blocks also reset
// the readiness flags for the next graph replay.
// ---------------------------------------------------------------------------
__device__ float blockSum(float v) {
    __shared__ float sw[8];
    int lane = threadIdx.x & 31, w = threadIdx.x >> 5;
    __syncthreads();
    #pragma unroll
    for (int o = 16; o; o >>= 1) v += __shfl_xor_sync(0xffffffffu, v, o);
    if (lane == 0) sw[w] = v;
    __syncthreads();
    v = (threadIdx.x < 8) ? sw[threadIdx.x] : 0.0f;
    if (w == 0)
        #pragma unroll
        for (int o = 4; o; o >>= 1) v += __shfl_xor_sync(0xffu, v, o);
    return v;
}

__global__ __launch_bounds__(256) void k_red(float* __restrict__ out) {
    int bid = blockIdx.x, tid = threadIdx.x;
    if (bid < 768) {
        int bt = bid >> 4, seg = bid & 15;
        const float* g = g_GvvP + (size_t)bt * KSPLIT * TILE * TILE + seg * 1024;
        float total = 0.0f;
        #pragma unroll
        for (int i = tid; i < 1024; i += 256) {
            float x = 0.0f;
            #pragma unroll
            for (int kc = 0; kc < KSPLIT; kc++) x += g[kc * TILE * TILE + i];
            total += x * x;
        }
        total = blockSum(total);
        if (tid == 0) {
            float w = (bt % 3 == 1) ? 2.0f : 1.0f;  // off-diagonal tile counts twice
            atomicAdd(g_acc, w * total);
        }
    } else {
        int b = bid - 768;
        if (tid < 32) g_rdy[b * 32 + tid] = 0u;   // reset flags for next replay
        const float* gp = g_GvyP + (size_t)b * 32 * 1024;
        float gy = 0.0f;
        #pragma unroll
        for (int j = 0; j < 4; j++) {
            int o = tid + 256 * j;
            float x = 0.0f;
            #pragma unroll
            for (int ch = 0; ch < 32; ch++) x += gp[ch * 1024 + o];
            gy += x * x;
        }
        float c0 = 0, c1 = 0, c2 = 0, c3 = 0;
        for (int t = tid; t < T_; t += 256) {
            int s = g_cls[b * T_ + t];
            c0 += (s == 0); c1 += (s == 1); c2 += (s == 2); c3 += (s == 3);
        }
        gy = blockSum(gy);
        c0 = blockSum(c0); c1 = blockSum(c1); c2 = blockSum(c2); c3 = blockSum(c3);
        if (tid == 0)
            atomicAdd(g_acc, -2.0f * gy + c0 * c0 + c1 * c1 + c2 * c2 + c3 * c3);
    }
    // last block to finish writes the output, then resets for the next replay
    if (tid == 0) {
        __threadfence();
        unsigned old = atomicAdd(&g_done, 1u);
        if (old == NRED - 1) {
            // divide by T*T*B = 2^32 (exact power of two)
            out[0] = g_acc[0] * 2.3283064365386963e-10f;
            g_acc[0] = 0.0f;
            g_done = 0u;
        }
    }
}

// ---------------------------------------------------------------------------
extern "C" void kernel_launch(void* const* d_in, const int* in_sizes, int n_in,
                              void* d_out, int out_size) {
    const float* emb = (const float*)d_in[0];
    const float* lab = (const float*)d_in[1];
    float* out = (float*)d_out;
    (void)in_sizes; (void)n_in; (void)out_size;

    const int smem_bytes = 2 * NSTAGE * MS * (int)sizeof(__nv_bfloat16);  // 69632
    cudaFuncSetAttribute(k_fused, cudaFuncAttributeMaxDynamicSharedMemorySize, smem_bytes);

    k_fused<<<512 + 48 * KSPLIT, 256, smem_bytes>>>(emb, lab);  // norm + gram overlapped
    k_red<<<NRED, 256>>>(out);
}

// round 17
// speedup vs baseline: 1.0583x; 1.0583x over previous
#include <cuda_runtime.h>
#include <cuda_bf16.h>
#include <cstdint>

// Problem constants
#define B_ 16
#define T_ 16384
#define D_ 256
#define S_ 4
#define TILE 128
#define KT 64
#define KSPLIT 6               // 48*6 = 288 CTAs = 2 per SM
#define PITCH 136              // 128 + 8 pad -> conflict-free ldmatrix.trans
#define MS (KT * PITCH)        // elements per smem matrix stage
#define NSTAGE 2
#define NRED 400               // 384 Gvv blocks + 16 Gvy/count blocks

// Scratch (device globals; zero-initialized at load)
__device__ __nv_bfloat16 g_V[(size_t)B_ * T_ * D_];         // normalized V, bf16
__device__ unsigned char g_cls[B_ * T_];                     // speaker class per row
__device__ float g_GvvP[(size_t)48 * KSPLIT * TILE * TILE];  // K-split partials (18.9MB)
__device__ float g_GvyP[512 * 1024];                         // per-block Gvy partials (2MB)
__device__ float g_acc[1];
__device__ unsigned int g_done;

// ---------------------------------------------------------------------------
// K1: fused row-wise L2 normalize (fp32 -> bf16) + class extraction + Gvy
// partials. 512 blocks, 8 warps, warp = 64 rows processed 4 at a time
// (batched LDG.128 + interleaved shfl butterflies). [R9 exact]
// ---------------------------------------------------------------------------
__global__ __launch_bounds__(256) void k_norm(const float* __restrict__ emb,
                                              const float* __restrict__ lab) {
    __shared__ float sred[8 * 1024];
    int b    = blockIdx.x >> 5;
    int ch   = blockIdx.x & 31;
    int wid  = threadIdx.x >> 5, lane = threadIdx.x & 31;
    int row0 = b * T_ + ch * 512 + wid * 64;

    // coalesced class pre-load: lane l handles rows row0+l and row0+32+l
    int s_lo, s_hi;
    {
        float4 lb = reinterpret_cast<const float4*>(lab)[row0 + lane];
        s_lo = lb.y > 0.5f ? 1 : (lb.z > 0.5f ? 2 : (lb.w > 0.5f ? 3 : 0));
        g_cls[row0 + lane] = (unsigned char)s_lo;
        float4 lb2 = reinterpret_cast<const float4*>(lab)[row0 + 32 + lane];
        s_hi = lb2.y > 0.5f ? 1 : (lb2.z > 0.5f ? 2 : (lb2.w > 0.5f ? 3 : 0));
        g_cls[row0 + 32 + lane] = (unsigned char)s_hi;
    }

    float acc[4][8];
    #pragma unroll
    for (int c = 0; c < 4; c++)
        #pragma unroll
        for (int i = 0; i < 8; i++) acc[c][i] = 0.0f;

    #pragma unroll 1
    for (int rb = 0; rb < 64; rb += 4) {
        // batch loads: 8 independent LDG.128 per lane
        float4 va[4][2];
        #pragma unroll
        for (int u = 0; u < 4; u++) {
            const float4* src = reinterpret_cast<const float4*>(emb)
                              + (size_t)(row0 + rb + u) * (D_ / 4) + lane * 2;
            va[u][0] = src[0];
            va[u][1] = src[1];
        }
        // 4 independent reductions, interleaved butterflies
        float ss[4];
        #pragma unroll
        for (int u = 0; u < 4; u++) {
            float4 v0 = va[u][0], v1 = va[u][1];
            ss[u] = v0.x*v0.x + v0.y*v0.y + v0.z*v0.z + v0.w*v0.w
                  + v1.x*v1.x + v1.y*v1.y + v1.z*v1.z + v1.w*v1.w;
        }
        #pragma unroll
        for (int o = 16; o; o >>= 1) {
            #pragma unroll
            for (int u = 0; u < 4; u++)
                ss[u] += __shfl_xor_sync(0xffffffffu, ss[u], o);
        }
        #pragma unroll
        for (int u = 0; u < 4; u++) {
            int r = rb + u;
            float sc = 1.0f / fmaxf(sqrtf(ss[u]), 1e-12f);
            float4 v0 = va[u][0], v1 = va[u][1];
            float n0 = v0.x * sc, n1 = v0.y * sc, n2 = v0.z * sc, n3 = v0.w * sc;
            float n4 = v1.x * sc, n5 = v1.y * sc, n6 = v1.z * sc, n7 = v1.w * sc;

            __nv_bfloat162 p0 = __floats2bfloat162_rn(n0, n1);
            __nv_bfloat162 p1 = __floats2bfloat162_rn(n2, n3);
            __nv_bfloat162 p2 = __floats2bfloat162_rn(n4, n5);
            __nv_bfloat162 p3 = __floats2bfloat162_rn(n6, n7);
            uint4 pk;
            pk.x = *reinterpret_cast<uint32_t*>(&p0);
            pk.y = *reinterpret_cast<uint32_t*>(&p1);
            pk.z = *reinterpret_cast<uint32_t*>(&p2);
            pk.w = *reinterpret_cast<uint32_t*>(&p3);
            reinterpret_cast<uint4*>(g_V)[(size_t)(row0 + r) * (D_ / 8) + lane] = pk;

            int s = __shfl_sync(0xffffffffu, r < 32 ? s_lo : s_hi, r & 31);
            #define ACCUM(C) { acc[C][0]+=n0; acc[C][1]+=n1; acc[C][2]+=n2; acc[C][3]+=n3; \
                               acc[C][4]+=n4; acc[C][5]+=n5; acc[C][6]+=n6; acc[C][7]+=n7; }
            if      (s == 0) ACCUM(0)
            else if (s == 1) ACCUM(1)
            else if (s == 2) ACCUM(2)
            else             ACCUM(3)
            #undef ACCUM
        }
    }

    // cross-warp reduce: sred[wid][(c*8+i)*32 + lane]  (conflict-free)
    #pragma unroll
    for (int c = 0; c < 4; c++)
        #pragma unroll
        for (int i = 0; i < 8; i++)
            sred[wid * 1024 + (c * 8 + i) * 32 + lane] = acc[c][i];
    __syncthreads();

    // per-block Gvy partial: plain coalesced stores, k_red sums the 32 slots
    float* gp = g_GvyP + (size_t)blockIdx.x * 1024;
    #pragma unroll
    for (int j = 0; j < 4; j++) {
        int o = threadIdx.x + 256 * j;
        float sum = 0.0f;
        #pragma unroll
        for (int w = 0; w < 8; w++) sum += sred[w * 1024 + o];
        gp[o] = sum;
    }
}

// ---------------------------------------------------------------------------
// PTX helpers
// ---------------------------------------------------------------------------
__device__ __forceinline__ void cp16(__nv_bfloat16* dst, const __nv_bfloat16* src) {
    unsigned d = (unsigned)__cvta_generic_to_shared(dst);
    asm volatile("cp.async.cg.shared.global [%0], [%1], 16;\n" :: "r"(d), "l"(src));
}
__device__ __forceinline__ void cp_commit() { asm volatile("cp.async.commit_group;\n"); }
template <int N> __device__ __forceinline__ void cp_wait() {
    asm volatile("cp.async.wait_group %0;\n" :: "n"(N));
}
__device__ __forceinline__ void ldsm4t(uint32_t* r, const __nv_bfloat16* p) {
    unsigned a = (unsigned)__cvta_generic_to_shared(p);
    asm volatile("ldmatrix.sync.aligned.m8n8.x4.trans.shared.b16 {%0,%1,%2,%3}, [%4];\n"
                 : "=r"(r[0]), "=r"(r[1]), "=r"(r[2]), "=r"(r[3]) : "r"(a));
}
__device__ __forceinline__ void mma_bf16(float* c, const uint32_t* a, const uint32_t* b) {
    asm volatile("mma.sync.aligned.m16n8k16.row.col.f32.bf16.bf16.f32 "
                 "{%0,%1,%2,%3},{%4,%5,%6,%7},{%8,%9},{%0,%1,%2,%3};\n"
                 : "+f"(c[0]), "+f"(c[1]), "+f"(c[2]), "+f"(c[3])
                 : "r"(a[0]), "r"(a[1]), "r"(a[2]), "r"(a[3]), "r"(b[0]), "r"(b[1]));
}

// ---------------------------------------------------------------------------
// K2: Gram tiles Gvv = V^T V. grid (48, 6) = 288 CTAs = 2/SM. [R9 exact:
// 8 warps, 32x64 warp tiles, 2-stage ring, one __syncthreads per iter.]
// K-iterations: 43,43,43,43,42,42 (sum 256).
// ---------------------------------------------------------------------------
__global__ __launch_bounds__(256, 2) void k_gram() {
    extern __shared__ __nv_bfloat16 sm[];
    int bt   = blockIdx.x;
    int b    = bt / 3, tile = bt % 3;
    int ti   = (tile == 0) ? 0 : 1;
    int tj   = (tile == 2) ? 1 : 0;
    bool diag = (ti == tj);
    int kc   = blockIdx.y;
    int it0  = (kc < 4) ? 43 * kc : 172 + 42 * (kc - 4);
    int NIT  = (kc < 4) ? 43 : 42;
    int tid  = threadIdx.x;
    const __nv_bfloat16* gv = g_V + (size_t)b * T_ * D_;

    int wid = tid >> 5, lane = tid & 31;
    int wm = (wid & 3) * 32;
    int wn = (wid >> 2) * 64;
    int q = lane >> 3, rr = lane & 7;

    float acc[2][8][4];
    #pragma unroll
    for (int mi = 0; mi < 2; mi++)
        #pragma unroll
        for (int ni = 0; ni < 8; ni++)
            #pragma unroll
            for (int x = 0; x < 4; x++) acc[mi][ni][x] = 0.0f;

    auto load_stage = [&](int st, int iter) {
        size_t kofs = (size_t)(it0 + iter) * KT;
        const __nv_bfloat16* ga = gv + kofs * D_ + ti * TILE;
        __nv_bfloat16* sa = sm + st * MS;
        #pragma unroll
        for (int i = 0; i < 4; i++) {
            int c = tid + i * 256;
            int r = c >> 4, cc = c & 15;
            cp16(sa + r * PITCH + cc * 8, ga + r * D_ + cc * 8);
        }
        if (!diag) {
            const __nv_bfloat16* gb = gv + kofs * D_ + tj * TILE;
            __nv_bfloat16* sb = sm + (NSTAGE + st) * MS;
            #pragma unroll
            for (int i = 0; i < 4; i++) {
                int c = tid + i * 256;
                int r = c >> 4, cc = c & 15;
                cp16(sb + r * PITCH + cc * 8, gb + r * D_ + cc * 8);
            }
        }
        cp_commit();
    };

    load_stage(0, 0);

    for (int it = 0; it < NIT; ++it) {
        cp_wait<0>();          // stage (it&1) landed
        __syncthreads();       // all warps past compute(it-1): stage (it+1)&1 free
        if (it + 1 < NIT) load_stage((it + 1) & 1, it + 1);

        int st = it & 1;
        const __nv_bfloat16* As = sm + st * MS;
        const __nv_bfloat16* Bs = diag ? As : sm + (NSTAGE + st) * MS;
        #pragma unroll
        for (int ks = 0; ks < KT / 16; ++ks) {
            uint32_t af[2][4];
            #pragma unroll
            for (int mi = 0; mi < 2; mi++) {
                int dm   = wm + mi * 16;
                int krow = ks * 16 + ((q & 2) ? 8 : 0) + rr;
                int col  = dm + ((q & 1) ? 8 : 0);
                ldsm4t(af[mi], As + krow * PITCH + col);
            }
            uint32_t bfr[8][2];
            #pragma unroll
            for (int j = 0; j < 4; j++) {
                int n0   = wn + j * 16;
                int krow = ks * 16 + ((q & 1) ? 8 : 0) + rr;
                int col  = n0 + ((q & 2) ? 8 : 0);
                uint32_t t4[4];
                ldsm4t(t4, Bs + krow * PITCH + col);
                bfr[2 * j][0]     = t4[0]; bfr[2 * j][1]     = t4[1];
                bfr[2 * j + 1][0] = t4[2]; bfr[2 * j + 1][1] = t4[3];
            }
            #pragma unroll
            for (int mi = 0; mi < 2; mi++)
                #pragma unroll
                for (int ni = 0; ni < 8; ni++)
                    mma_bf16(acc[mi][ni], af[mi], bfr[ni]);
        }
    }

    // Epilogue: plain stores of this K-split's partial tile
    int gid = lane >> 2, tig = lane & 3;
    float* gdst = g_GvvP + ((size_t)bt * KSPLIT + kc) * TILE * TILE;
    #pragma unroll
    for (int mi = 0; mi < 2; mi++) {
        #pragma unroll
        for (int ni = 0; ni < 8; ni++) {
            int m = wm + mi * 16 + gid;
            int n = wn + ni * 8 + tig * 2;
            float* p = gdst + m * TILE + n;
            p[0] = acc[mi][ni][0];
            p[1] = acc[mi][ni][1];
            p[8 * TILE + 0] = acc[mi][ni][2];
            p[8 * TILE + 1] = acc[mi][ni][3];
        }
    }
}

// ---------------------------------------------------------------------------
// K3: parallel reduction + final output, float4-vectorized. 400 blocks:
//   bid < 384: Gvv tile eighth (2048 elems) -> 12 LDG.128/thread
//   bid >= 384: per-batch Gvy (32 slots x 1024) -> 32 LDG.128/thread + counts
// Last block writes out and RESETS g_acc/g_done for the next graph replay.
// ---------------------------------------------------------------------------
__device__ float blockSum(float v) {
    __shared__ float sw[8];
    int lane = threadIdx.x & 31, w = threadIdx.x >> 5;
    __syncthreads();
    #pragma unroll
    for (int o = 16; o; o >>= 1) v += __shfl_xor_sync(0xffffffffu, v, o);
    if (lane == 0) sw[w] = v;
    __syncthreads();
    v = (threadIdx.x < 8) ? sw[threadIdx.x] : 0.0f;
    if (w == 0)
        #pragma unroll
        for (int o = 4; o; o >>= 1) v += __shfl_xor_sync(0xffu, v, o);
    return v;
}

__global__ __launch_bounds__(256) void k_red(float* __restrict__ out) {
    int bid = blockIdx.x, tid = threadIdx.x;
    if (bid < 384) {
        int bt = bid >> 3, seg = bid & 7;
        // float4 view of this segment (2048 floats = 512 float4)
        const float4* g4 = reinterpret_cast<const float4*>(
            g_GvvP + (size_t)bt * KSPLIT * TILE * TILE + seg * 2048);
        const int P4 = TILE * TILE / 4;  // float4 stride between partials
        float total = 0.0f;
        #pragma unroll
        for (int v = 0; v < 2; v++) {
            int i = tid + 256 * v;
            float4 s = g4[i];
            #pragma unroll
            for (int kc = 1; kc < KSPLIT; kc++) {
                float4 p = g4[kc * P4 + i];
                s.x += p.x; s.y += p.y; s.z += p.z; s.w += p.w;
            }
            total += s.x * s.x + s.y * s.y + s.z * s.z + s.w * s.w;
        }
        total = blockSum(total);
        if (tid == 0) {
            float w = (bt % 3 == 1) ? 2.0f : 1.0f;  // off-diagonal tile counts twice
            atomicAdd(g_acc, w * total);
        }
    } else {
        int b = bid - 384;
        const float4* gp4 = reinterpret_cast<const float4*>(
            g_GvyP + (size_t)b * 32 * 1024);
        float4 s = gp4[tid];
        #pragma unroll
        for (int ch = 1; ch < 32; ch++) {
            float4 p = gp4[ch * 256 + tid];
            s.x += p.x; s.y += p.y; s.z += p.z; s.w += p.w;
        }
        float gy = s.x * s.x + s.y * s.y + s.z * s.z + s.w * s.w;
        float c0 = 0, c1 = 0, c2 = 0, c3 = 0;
        for (int t = tid; t < T_; t += 256) {
            int sc = g_cls[b * T_ + t];
            c0 += (sc == 0); c1 += (sc == 1); c2 += (sc == 2); c3 += (sc == 3);
        }
        gy = blockSum(gy);
        c0 = blockSum(c0); c1 = blockSum(c1); c2 = blockSum(c2); c3 = blockSum(c3);
        if (tid == 0)
            atomicAdd(g_acc, -2.0f * gy + c0 * c0 + c1 * c1 + c2 * c2 + c3 * c3);
    }
    // last block to finish writes the output, then resets for the next replay
    if (tid == 0) {
        __threadfence();
        unsigned old = atomicAdd(&g_done, 1u);
        if (old == NRED - 1) {
            // divide by T*T*B = 2^32 (exact power of two)
            out[0] = g_acc[0] * 2.3283064365386963e-10f;
            g_acc[0] = 0.0f;
            g_done = 0u;
        }
    }
}

// ---------------------------------------------------------------------------
extern "C" void kernel_launch(void* const* d_in, const int* in_sizes, int n_in,
                              void* d_out, int out_size) {
    const float* emb = (const float*)d_in[0];
    const float* lab = (const float*)d_in[1];
    float* out = (float*)d_out;
    (void)in_sizes; (void)n_in; (void)out_size;

    const int smem_bytes = 2 * NSTAGE * MS * (int)sizeof(__nv_bfloat16);  // 69632
    cudaFuncSetAttribute(k_gram, cudaFuncAttributeMaxDynamicSharedMemorySize, smem_bytes);

    k_norm<<<512, 256>>>(emb, lab);        // fused normalize + Gvy partials (R9)
    dim3 g2(48, KSPLIT);
    k_gram<<<g2, 256, smem_bytes>>>();     // 8 warps, 32x64 warp tiles (R9)
    k_red<<<NRED, 256>>>(out);             // float4-vectorized, 400 blocks
}